// round 7
// baseline (speedup 1.0000x reference)
#include <cuda_runtime.h>
#include <math.h>

#define BB 64
#define TT 512
#define FF 64
#define EE 256
#define HH 512
#define GG 2048   // 4*H
#define OO 128
#define NBLK 128

// ---------------- device scratch ----------------
__device__ float g_xg[(size_t)TT * NBLK * 64 * 16]; // [t][blk][cc(64)][bb(16)] 256MB
__device__ float g_Wc[GG * FF];                     // fused W_ih @ W_emb
__device__ float g_biasc[GG];
__device__ float g_Wp[32 * 512 * 64];               // permuted W_hh [jg][k][c]  4MB
__device__ float g_h[2][HH * 2 * BB];               // [buf][k][dup b: 2b,2b+1]  512KB
__device__ float g_hsum[BB * HH];                   // [b][k]
struct BarCnt { unsigned v; unsigned pad[63]; };
__device__ BarCnt g_cnt[8];
__device__ volatile unsigned g_bar_gen;

// ---------------- helpers ----------------
__device__ __forceinline__ void ffma2(unsigned long long& d, unsigned long long a,
                                      unsigned long long b) {
    asm("fma.rn.f32x2 %0, %1, %2, %3;" : "=l"(d) : "l"(a), "l"(b), "l"(d));
}
__device__ __forceinline__ unsigned long long dup2(float x) {
    unsigned long long r; unsigned u = __float_as_uint(x);
    asm("mov.b64 %0, {%1, %1};" : "=l"(r) : "r"(u));
    return r;
}
__device__ __forceinline__ float lo32(unsigned long long v) { return __uint_as_float((unsigned)v); }
__device__ __forceinline__ float hi32(unsigned long long v) { return __uint_as_float((unsigned)(v >> 32)); }

__device__ __forceinline__ void cpasync16(float* dst_smem, const float* src) {
    unsigned saddr = (unsigned)__cvta_generic_to_shared(dst_smem);
    asm volatile("cp.async.cg.shared.global [%0], [%1], 16;" :: "r"(saddr), "l"(src));
}
#define CP_COMMIT() asm volatile("cp.async.commit_group;")
#define CP_WAIT0()  asm volatile("cp.async.wait_group 0;")

__device__ __forceinline__ float ftanh(float x) {
    x = fminf(fmaxf(x, -15.f), 15.f);
    float e = __expf(2.f * x);
    return (e - 1.f) / (e + 1.f);
}
__device__ __forceinline__ float fsig(float x) { return 1.f / (1.f + __expf(-x)); }

// ---------------- 1. fuse weights ----------------
__global__ void fuse_weights_kernel(const float* __restrict__ Wih,
                                    const float* __restrict__ Wemb,
                                    const float* __restrict__ bemb,
                                    const float* __restrict__ bih,
                                    const float* __restrict__ bhh) {
    int g = blockIdx.x;
    int f = threadIdx.x;
    __shared__ float s[EE];
    for (int e = f; e < EE; e += 64) s[e] = Wih[g * EE + e];
    __syncthreads();
    float acc = 0.f;
#pragma unroll 8
    for (int e = 0; e < EE; e++) acc += s[e] * Wemb[e * FF + f];
    g_Wc[g * FF + f] = acc;
    if (f == 0) {
        float bb = 0.f;
        for (int e = 0; e < EE; e++) bb += s[e] * bemb[e];
        g_biasc[g] = bb + bih[g] + bhh[g];
    }
}

// ---------------- 1b. permute W_hh -> g_Wp[jg][k][c], c = gate*16 + jj ------
__global__ void permute_whh_kernel(const float* __restrict__ Whh) {
    int g = blockIdx.x;                 // 0..2047: g = gate*512 + j
    int gate = g >> 9, j = g & 511;
    int jg = j >> 4, jj = j & 15;
    int c = gate * 16 + jj;
    for (int k = threadIdx.x; k < 512; k += 128)
        g_Wp[((size_t)jg * 512 + k) * 64 + c] = Whh[(size_t)g * 512 + k];
}

// ---------------- 2. xg = x @ Wc^T + biasc, out [t][blk][cc][bb] ------------
__global__ __launch_bounds__(256) void xg_kernel(const float* __restrict__ x) {
    __shared__ __align__(16) float xs[FF][68];
    __shared__ __align__(16) float ws[FF][68];
    int tb = blockIdx.x;                  // token t
    int cbase = blockIdx.y * 64;
    int tid = threadIdx.x;
#pragma unroll
    for (int i = 0; i < 16; i++) {
        int idx = i * 256 + tid;
        int r = idx >> 6, k = idx & 63;
        xs[k][r] = x[((size_t)r * TT + tb) * FF + k];
        ws[k][r] = g_Wc[(size_t)(cbase + r) * FF + k];
    }
    __syncthreads();
    int rg = tid & 15, cg = tid >> 4;
    int r0 = rg * 4, c0 = cg * 4;
    unsigned long long acc[4][2] = {};
#pragma unroll 4
    for (int k = 0; k < FF; k++) {
        float4 hv = *(const float4*)&xs[k][r0];
        ulonglong2 wv = *(const ulonglong2*)&ws[k][c0];
        unsigned long long h0 = dup2(hv.x), h1 = dup2(hv.y), h2 = dup2(hv.z), h3 = dup2(hv.w);
        ffma2(acc[0][0], h0, wv.x); ffma2(acc[0][1], h0, wv.y);
        ffma2(acc[1][0], h1, wv.x); ffma2(acc[1][1], h1, wv.y);
        ffma2(acc[2][0], h2, wv.x); ffma2(acc[2][1], h2, wv.y);
        ffma2(acc[3][0], h3, wv.x); ffma2(acc[3][1], h3, wv.y);
    }
    int bg = r0 >> 4, bb = r0 & 15;
#pragma unroll
    for (int j = 0; j < 4; j++) {
        int g = cbase + c0 + j;
        float bias = g_biasc[g];
        int gate = g >> 9, jcol = g & 511;
        int jg = jcol >> 4, jj = jcol & 15;
        int blk = jg * 4 + bg;
        int cc = gate * 16 + jj;
        float4 v;
        v.x = ((j & 1) ? hi32(acc[0][j >> 1]) : lo32(acc[0][j >> 1])) + bias;
        v.y = ((j & 1) ? hi32(acc[1][j >> 1]) : lo32(acc[1][j >> 1])) + bias;
        v.z = ((j & 1) ? hi32(acc[2][j >> 1]) : lo32(acc[2][j >> 1])) + bias;
        v.w = ((j & 1) ? hi32(acc[3][j >> 1]) : lo32(acc[3][j >> 1])) + bias;
        *(float4*)&g_xg[(((size_t)tb * NBLK + blk) * 64 + cc) * 16 + bb] = v;
    }
}

// ---------------- 3. init ----------------
__global__ void init_state_kernel() {
    int i = blockIdx.x * 256 + threadIdx.x;
    if (i < HH * 2 * BB) g_h[0][i] = 0.f;
    if (i < 8) g_cnt[i].v = 0u;
    if (i == 0) g_bar_gen = 0u;
}

// ---------------- 4. persistent LSTM ----------------
// 128 blocks x 512 threads. Block (jg, bg): 16 hidden units x 16 batches.
// smem: W [512k][64c] 128KB | hdup [512k][32] 64KB | red [8kg][16b str68][64c] 34KB
__global__ __launch_bounds__(512, 1) void lstm_persist() {
    extern __shared__ __align__(16) float smem[];
    float* ws  = smem;                 // 32768 floats
    float* hs  = smem + 32768;         // 16384 floats (dup)
    float* red = smem + 49152;         // 8*16*68 = 8704 floats

    int tid = threadIdx.x;
    int blk = blockIdx.x;
    int jg = blk >> 2, bg = blk & 3;

    int w = tid >> 5, lane = tid & 31;
    int kg = w & 7, half = w >> 3;     // kg: k-slice, half: col half
    int colg = lane & 7, bg4 = lane >> 3;
    int c0 = half * 32 + colg * 4;
    int b0 = bg4 * 4;                  // local batch base (0..12)

    // epilogue mapping (threads 0..255): jj = tid>>4, bb = tid&15
    int ejj = tid >> 4, ebb = tid & 15;

    // ---- load W slice: 128KB coalesced from permuted copy ----
    {
        const float* src = g_Wp + (size_t)jg * 512 * 64;
#pragma unroll
        for (int i = 0; i < 16; i++)
            cpasync16(ws + (i * 512 + tid) * 4, src + (i * 512 + tid) * 4);
        CP_COMMIT();
        CP_WAIT0();
        __syncthreads();
    }

    float c_reg = 0.f, hsum_reg = 0.f;

    for (int t = 0; t < TT; t++) {
        const float* hcur = g_h[t & 1];
        float* hnxt = g_h[(t + 1) & 1];

        // prefetch xg gate values (threads 0..255)
        float xv0 = 0.f, xv1 = 0.f, xv2 = 0.f, xv3 = 0.f;
        if (tid < 256) {
            const float* xp = g_xg + ((size_t)t * NBLK + blk) * 1024 + ejj * 16 + ebb;
            xv0 = __ldcg(xp); xv1 = __ldcg(xp + 256);
            xv2 = __ldcg(xp + 512); xv3 = __ldcg(xp + 768);
        }

        // warp loads 32 dup-rows (128B each) of its k-slice half
        {
            int rowbase = kg * 64 + half * 32;
            const float* srcb = hcur + bg * 32;
#pragma unroll
            for (int i = 0; i < 8; i++) {
                int e = i * 32 + lane;
                int row = rowbase + (e >> 3), seg = e & 7;
                cpasync16(hs + row * 32 + seg * 4, srcb + row * 128 + seg * 4);
            }
            CP_COMMIT();
            CP_WAIT0();
            // pair barrier: warps kg and kg+8 wrote the two halves
            asm volatile("bar.sync %0, 64;" :: "r"(1 + kg) : "memory");
        }

        // GEMM: 64 k x (4 cols x 4 batches) per lane, acc f32x2 over col pairs
        unsigned long long acc[4][2] = {};
        const float* wsl = ws + (size_t)kg * 64 * 64 + c0;
        const float* hsl = hs + (size_t)kg * 64 * 32 + b0 * 2;
#pragma unroll 4
        for (int kk = 0; kk < 64; kk++) {
            ulonglong2 wv = *(const ulonglong2*)&wsl[kk * 64];
            unsigned long long h0 = *(const unsigned long long*)&hsl[kk * 32];
            unsigned long long h1 = *(const unsigned long long*)&hsl[kk * 32 + 2];
            unsigned long long h2 = *(const unsigned long long*)&hsl[kk * 32 + 4];
            unsigned long long h3 = *(const unsigned long long*)&hsl[kk * 32 + 6];
            ffma2(acc[0][0], h0, wv.x); ffma2(acc[0][1], h0, wv.y);
            ffma2(acc[1][0], h1, wv.x); ffma2(acc[1][1], h1, wv.y);
            ffma2(acc[2][0], h2, wv.x); ffma2(acc[2][1], h2, wv.y);
            ffma2(acc[3][0], h3, wv.x); ffma2(acc[3][1], h3, wv.y);
        }

        // partials -> red[kg][b(str68)][c]
#pragma unroll
        for (int i = 0; i < 4; i++) {
            float4 v;
            v.x = lo32(acc[i][0]); v.y = hi32(acc[i][0]);
            v.z = lo32(acc[i][1]); v.w = hi32(acc[i][1]);
            *(float4*)&red[kg * 1088 + (b0 + i) * 68 + c0] = v;
        }
        __syncthreads();

        // epilogue (threads 0..255): reduce 8 partials, activations, update
        if (tid < 256) {
            float gs0 = 0.f, gs1 = 0.f, gs2 = 0.f, gs3 = 0.f;
#pragma unroll
            for (int q = 0; q < 8; q++) {
                const float* rr = red + q * 1088 + ebb * 68 + ejj;
                gs0 += rr[0]; gs1 += rr[16]; gs2 += rr[32]; gs3 += rr[48];
            }
            float iv = fsig(gs0 + xv0);
            float fv = fsig(gs1 + xv1);
            float gv = ftanh(gs2 + xv2);
            float ov = fsig(gs3 + xv3);
            c_reg = fv * c_reg + iv * gv;
            float hn = ov * ftanh(c_reg);
            int j = jg * 16 + ejj;
            int b = bg * 16 + ebb;
            *(unsigned long long*)&hnxt[j * 128 + 2 * b] = dup2(hn);  // dup store
            hsum_reg += hn;
        }

        // grid barrier
        if (t < TT - 1) {
            __threadfence();
            __syncthreads();
            if (tid == 0) {
                unsigned want = 16u * (unsigned)(t + 1);
                atomicAdd(&g_cnt[blk & 7].v, 1u);
                if (blk == 0) {
                    for (int i = 0; i < 8; i++)
                        while (*(volatile unsigned*)&g_cnt[i].v < want) { }
                    __threadfence();
                    g_bar_gen = (unsigned)(t + 1);
                } else {
                    while (g_bar_gen < (unsigned)(t + 1)) { }
                    __threadfence();
                }
            }
            __syncthreads();
        }
    }
    if (tid < 256) {
        int j = jg * 16 + ejj;
        int b = bg * 16 + ebb;
        g_hsum[b * HH + j] = hsum_reg;
    }
}

// ---------------- 5. pool + FC ----------------
__global__ void pool_fc_kernel(const float* __restrict__ Wfc,
                               const float* __restrict__ bfc,
                               float* __restrict__ out) {
    int b = blockIdx.x;
    __shared__ float sh[HH];
    int tid = threadIdx.x;
    for (int k = tid; k < HH; k += 256) sh[k] = g_hsum[b * HH + k];
    __syncthreads();
    int warp = tid >> 5, lane = tid & 31;
    for (int o = warp; o < OO; o += 8) {
        float a = 0.f;
        for (int k = lane; k < HH; k += 32) a += sh[k] * Wfc[o * HH + k];
#pragma unroll
        for (int s = 16; s; s >>= 1) a += __shfl_xor_sync(0xffffffffu, a, s);
        if (lane == 0) out[b * OO + o] = a * (1.f / 512.f) + bfc[o];
    }
}

extern "C" void kernel_launch(void* const* d_in, const int* in_sizes, int n_in,
                              void* d_out, int out_size) {
    const float* x    = (const float*)d_in[0];
    const float* Wemb = (const float*)d_in[1];
    const float* bemb = (const float*)d_in[2];
    const float* Wih  = (const float*)d_in[3];
    const float* Whh  = (const float*)d_in[4];
    const float* bih  = (const float*)d_in[5];
    const float* bhh  = (const float*)d_in[6];
    const float* Wfc  = (const float*)d_in[7];
    const float* bfc  = (const float*)d_in[8];
    float* out = (float*)d_out;

    static bool attr_set = false;
    if (!attr_set) {
        cudaFuncSetAttribute(lstm_persist, cudaFuncAttributeMaxDynamicSharedMemorySize, 231424);
        attr_set = true;
    }

    fuse_weights_kernel<<<GG, 64>>>(Wih, Wemb, bemb, bih, bhh);
    permute_whh_kernel<<<GG, 128>>>(Whh);

    dim3 xgrid(TT, GG / 64);
    xg_kernel<<<xgrid, 256>>>(x);

    init_state_kernel<<<(HH * 2 * BB + 255) / 256, 256>>>();

    lstm_persist<<<NBLK, 512, 231424>>>();

    pool_fc_kernel<<<BB, 256>>>(Wfc, bfc, out);
}

// round 8
// speedup vs baseline: 1.3828x; 1.3828x over previous
#include <cuda_runtime.h>
#include <math.h>

#define BB 64
#define TT 512
#define FF 64
#define EE 256
#define HH 512
#define GG 2048   // 4*H
#define OO 128
#define NBLK 128

// ---------------- device scratch (no allocations allowed) ----------------
__device__ float g_xg[(size_t)TT * NBLK * 16 * 64];  // [t][blk][c(16)][b(64)]  256 MB
__device__ float g_Wc[GG * FF];                      // fused W_ih @ W_emb
__device__ float g_biasc[GG];
__device__ float g_h[2][HH * BB];                    // [buf][k][b]  k-major
__device__ float g_hsum[BB * HH];                    // [b][k]
struct BarCnt { unsigned v; unsigned pad[63]; };     // 256B apart -> distinct L2 sets
__device__ BarCnt g_cnt[8];

// ---------------- f32x2 helpers ----------------
__device__ __forceinline__ void ffma2(unsigned long long& d, unsigned long long a,
                                      unsigned long long b) {
    asm("fma.rn.f32x2 %0, %1, %2, %3;" : "=l"(d) : "l"(a), "l"(b), "l"(d));
}
__device__ __forceinline__ unsigned long long dup2(float x) {
    unsigned long long r; unsigned u = __float_as_uint(x);
    asm("mov.b64 %0, {%1, %1};" : "=l"(r) : "r"(u));
    return r;
}
__device__ __forceinline__ float lo32(unsigned long long v) { return __uint_as_float((unsigned)v); }
__device__ __forceinline__ float hi32(unsigned long long v) { return __uint_as_float((unsigned)(v >> 32)); }

__device__ __forceinline__ void cpasync16(float* dst_smem, const float* src) {
    unsigned saddr = (unsigned)__cvta_generic_to_shared(dst_smem);
    asm volatile("cp.async.cg.shared.global [%0], [%1], 16;" :: "r"(saddr), "l"(src));
}
#define CP_COMMIT() asm volatile("cp.async.commit_group;")
#define CP_WAITN(n) asm volatile("cp.async.wait_group %0;" :: "n"(n))

__device__ __forceinline__ float ftanh(float x) {
    x = fminf(fmaxf(x, -15.f), 15.f);
    float e = __expf(2.f * x);
    return (e - 1.f) / (e + 1.f);
}
__device__ __forceinline__ float fsig(float x) { return 1.f / (1.f + __expf(-x)); }

// ---------------- 1. fuse weights: Wc = W_ih @ W_emb ----------------
__global__ void fuse_weights_kernel(const float* __restrict__ Wih,
                                    const float* __restrict__ Wemb,
                                    const float* __restrict__ bemb,
                                    const float* __restrict__ bih,
                                    const float* __restrict__ bhh) {
    int g = blockIdx.x;
    int f = threadIdx.x;
    __shared__ float s[EE];
    for (int e = f; e < EE; e += 64) s[e] = Wih[g * EE + e];
    __syncthreads();
    float acc = 0.f;
#pragma unroll 8
    for (int e = 0; e < EE; e++) acc += s[e] * Wemb[e * FF + f];
    g_Wc[g * FF + f] = acc;
    if (f == 0) {
        float bb = 0.f;
        for (int e = 0; e < EE; e++) bb += s[e] * bemb[e];
        g_biasc[g] = bb + bih[g] + bhh[g];
    }
}

// ---------------- 2. xg = x @ Wc^T + biasc, permuted out [t][blk][c][b] --------
__global__ __launch_bounds__(256) void xg_kernel(const float* __restrict__ x) {
    __shared__ __align__(16) float xs[FF][68];   // [k][b]
    __shared__ __align__(16) float ws[FF][68];   // [k][col]
    int tb = blockIdx.x;                  // token index t
    int cbase = blockIdx.y * 64;
    int tid = threadIdx.x;
#pragma unroll
    for (int i = 0; i < 16; i++) {
        int idx = i * 256 + tid;
        int r = idx >> 6, k = idx & 63;
        xs[k][r] = x[((size_t)r * TT + tb) * FF + k];           // b = r
        ws[k][r] = g_Wc[(size_t)(cbase + r) * FF + k];
    }
    __syncthreads();
    int rg = tid & 15, cg = tid >> 4;
    int r0 = rg * 4, c0 = cg * 4;
    unsigned long long acc[4][2] = {};
#pragma unroll 4
    for (int k = 0; k < FF; k++) {
        float4 hv = *(const float4*)&xs[k][r0];
        ulonglong2 wv = *(const ulonglong2*)&ws[k][c0];
        unsigned long long h0 = dup2(hv.x), h1 = dup2(hv.y), h2 = dup2(hv.z), h3 = dup2(hv.w);
        ffma2(acc[0][0], h0, wv.x); ffma2(acc[0][1], h0, wv.y);
        ffma2(acc[1][0], h1, wv.x); ffma2(acc[1][1], h1, wv.y);
        ffma2(acc[2][0], h2, wv.x); ffma2(acc[2][1], h2, wv.y);
        ffma2(acc[3][0], h3, wv.x); ffma2(acc[3][1], h3, wv.y);
    }
#pragma unroll
    for (int j = 0; j < 4; j++) {
        int g = cbase + c0 + j;
        float bias = g_biasc[g];
        int blk = (g & 511) >> 2;
        int cc = ((g >> 9) << 2) + (g & 3);
        float4 v;
        v.x = ((j & 1) ? hi32(acc[0][j >> 1]) : lo32(acc[0][j >> 1])) + bias;
        v.y = ((j & 1) ? hi32(acc[1][j >> 1]) : lo32(acc[1][j >> 1])) + bias;
        v.z = ((j & 1) ? hi32(acc[2][j >> 1]) : lo32(acc[2][j >> 1])) + bias;
        v.w = ((j & 1) ? hi32(acc[3][j >> 1]) : lo32(acc[3][j >> 1])) + bias;
        *(float4*)&g_xg[((((size_t)tb * NBLK + blk) * 16 + cc) << 6) + r0] = v;
    }
}

// ---------------- 3. init ----------------
__global__ void init_state_kernel() {
    int i = blockIdx.x * 256 + threadIdx.x;
    if (i < HH * BB) g_h[0][i] = 0.f;
    if (i < 8) g_cnt[i].v = 0u;
}

// ---------------- 4. persistent LSTM: all 512 steps in one kernel ------------
// 128 blocks x 256 threads. Block owns 4 hidden units (16 gate-cols).
// smem: W plain [512k][16c] 32KB | h [512k][64b] 128KB | red [8][64 str17][16] 34KB
// 8-way k-split; each warp pipelines its own 64-k h slice in 4 cp.async groups
// (no block syncs in the GEMM phase). Parallel-poll grid barrier between steps.
__global__ __launch_bounds__(256, 1) void lstm_persist(const float* __restrict__ Whh) {
    extern __shared__ __align__(16) float smem[];
    float* ws  = smem;                 // 8192 floats
    float* hs  = smem + 8192;          // 32768 floats
    float* red = smem + 40960;         // 8*64*17 = 8704 floats

    int tid = threadIdx.x;
    int blk = blockIdx.x;
    int j0 = blk * 4;

    // GEMM mapping: warp kg owns k in [kg*64, kg*64+64)
    int kg = tid >> 5;                 // warp id 0..7
    int lane = tid & 31;
    int b0 = (lane & 7) * 8;           // 8 batches
    int c0 = (lane >> 3) * 4;          // 4 gate-cols

    // epilogue mapping: one thread per (b, jj)
    int eb = tid & 63, ejj = tid >> 6;

    // load W_hh slice (16 cols x 512 k), plain floats [k][16]
    for (int idx = tid; idx < 16 * 512; idx += 256) {
        int k = idx >> 4, c = idx & 15;
        int g = ((c >> 2) << 9) + j0 + (c & 3);   // gate*512 + j
        ws[k * 16 + c] = Whh[(size_t)g * HH + k];
    }
    __syncthreads();

    float c_reg = 0.f, hsum_reg = 0.f;

    const float* hsl = hs + kg * 4096;
    const float* wsl = ws + kg * 64 * 16;

    for (int t = 0; t < TT; t++) {
        const float* hcur = g_h[t & 1];
        float* hnxt = g_h[(t + 1) & 1];

        // prefetch this step's xg gate values (consumed ~5k cyc later)
        const float* xp = g_xg + (size_t)t * (NBLK * 1024) + ((size_t)blk * 16 + ejj) * 64 + eb;
        float xv0 = __ldcg(xp), xv1 = __ldcg(xp + 256), xv2 = __ldcg(xp + 512), xv3 = __ldcg(xp + 768);

        // issue warp-private h slice load as 4 pipelined groups (16 k-rows = 4KB each)
        {
            int base = kg * 4096;
#pragma unroll
            for (int g = 0; g < 4; g++) {
#pragma unroll
                for (int i = 0; i < 8; i++) {
                    int off = base + g * 1024 + (i * 32 + lane) * 4;
                    cpasync16(hs + off, hcur + off);
                }
                CP_COMMIT();
            }
        }

        unsigned long long acc[4][4] = {};   // [batch-pair][col]

#define GEMM_CHUNK(G)                                                              \
        {                                                                          \
            __syncwarp();                                                          \
            _Pragma("unroll 4")                                                    \
            for (int kk = (G)*16; kk < (G)*16 + 16; kk++) {                        \
                float4 wv = *(const float4*)&wsl[kk * 16 + c0];                    \
                unsigned long long w0 = dup2(wv.x), w1 = dup2(wv.y),               \
                                   w2 = dup2(wv.z), w3 = dup2(wv.w);               \
                ulonglong2 hA = *(const ulonglong2*)&hsl[kk * 64 + b0];            \
                ulonglong2 hB = *(const ulonglong2*)&hsl[kk * 64 + b0 + 4];        \
                ffma2(acc[0][0], hA.x, w0); ffma2(acc[0][1], hA.x, w1);            \
                ffma2(acc[0][2], hA.x, w2); ffma2(acc[0][3], hA.x, w3);            \
                ffma2(acc[1][0], hA.y, w0); ffma2(acc[1][1], hA.y, w1);            \
                ffma2(acc[1][2], hA.y, w2); ffma2(acc[1][3], hA.y, w3);            \
                ffma2(acc[2][0], hB.x, w0); ffma2(acc[2][1], hB.x, w1);            \
                ffma2(acc[2][2], hB.x, w2); ffma2(acc[2][3], hB.x, w3);            \
                ffma2(acc[3][0], hB.y, w0); ffma2(acc[3][1], hB.y, w1);            \
                ffma2(acc[3][2], hB.y, w2); ffma2(acc[3][3], hB.y, w3);            \
            }                                                                      \
        }

        CP_WAITN(3); GEMM_CHUNK(0)
        CP_WAITN(2); GEMM_CHUNK(1)
        CP_WAITN(1); GEMM_CHUNK(2)
        CP_WAITN(0); GEMM_CHUNK(3)
#undef GEMM_CHUNK

        // k-group partials -> red[kg][b][c] (stride 17 to avoid bank conflicts)
#pragma unroll
        for (int p = 0; p < 4; p++) {
            float* r0p = red + kg * 1088 + (b0 + 2 * p) * 17 + c0;
            float* r1p = r0p + 17;
#pragma unroll
            for (int j = 0; j < 4; j++) {
                r0p[j] = lo32(acc[p][j]);
                r1p[j] = hi32(acc[p][j]);
            }
        }
        __syncthreads();

        // epilogue: reduce 8 k-groups, activations, state update
        float gs0 = 0.f, gs1 = 0.f, gs2 = 0.f, gs3 = 0.f;
#pragma unroll
        for (int q = 0; q < 8; q++) {
            const float* rr = red + q * 1088 + eb * 17 + ejj;
            gs0 += rr[0]; gs1 += rr[4]; gs2 += rr[8]; gs3 += rr[12];
        }
        float iv = fsig(gs0 + xv0);
        float fv = fsig(gs1 + xv1);
        float gv = ftanh(gs2 + xv2);
        float ov = fsig(gs3 + xv3);
        c_reg = fv * c_reg + iv * gv;
        float hn = ov * ftanh(c_reg);
        hnxt[(j0 + ejj) * 64 + eb] = hn;   // [k][b] coalesced
        hsum_reg += hn;

        // grid barrier: arrive on distributed counters, parallel-poll all 8
        if (t < TT - 1) {
            __threadfence();               // release h stores
            __syncthreads();               // all threads' stores fenced
            if (tid == 0) atomicAdd(&g_cnt[blk & 7].v, 1u);
            if (tid < 8) {
                unsigned want = 16u * (unsigned)(t + 1);
                while (*(volatile unsigned*)&g_cnt[tid].v < want) { }
            }
            __syncthreads();
            __threadfence();
        }
    }
    g_hsum[eb * HH + j0 + ejj] = hsum_reg;
}

// ---------------- 5. pooled = hsum/512 ; out = pooled @ W_fc^T + b_fc --------
__global__ void pool_fc_kernel(const float* __restrict__ Wfc,
                               const float* __restrict__ bfc,
                               float* __restrict__ out) {
    int b = blockIdx.x;
    __shared__ float sh[HH];
    int tid = threadIdx.x;
    for (int k = tid; k < HH; k += 256) sh[k] = g_hsum[b * HH + k];
    __syncthreads();
    int warp = tid >> 5, lane = tid & 31;
    for (int o = warp; o < OO; o += 8) {
        float a = 0.f;
        for (int k = lane; k < HH; k += 32) a += sh[k] * Wfc[o * HH + k];
#pragma unroll
        for (int s = 16; s; s >>= 1) a += __shfl_xor_sync(0xffffffffu, a, s);
        if (lane == 0) out[b * OO + o] = a * (1.f / 512.f) + bfc[o];
    }
}

extern "C" void kernel_launch(void* const* d_in, const int* in_sizes, int n_in,
                              void* d_out, int out_size) {
    const float* x    = (const float*)d_in[0];
    const float* Wemb = (const float*)d_in[1];
    const float* bemb = (const float*)d_in[2];
    const float* Wih  = (const float*)d_in[3];
    const float* Whh  = (const float*)d_in[4];
    const float* bih  = (const float*)d_in[5];
    const float* bhh  = (const float*)d_in[6];
    const float* Wfc  = (const float*)d_in[7];
    const float* bfc  = (const float*)d_in[8];
    float* out = (float*)d_out;

    static bool attr_set = false;
    if (!attr_set) {
        cudaFuncSetAttribute(lstm_persist, cudaFuncAttributeMaxDynamicSharedMemorySize, 198656);
        attr_set = true;
    }

    fuse_weights_kernel<<<GG, 64>>>(Wih, Wemb, bemb, bih, bhh);

    dim3 xgrid(TT, GG / 64);
    xg_kernel<<<xgrid, 256>>>(x);

    init_state_kernel<<<(HH * BB + 255) / 256, 256>>>();

    lstm_persist<<<NBLK, 256, 198656>>>(Whh);

    pool_fc_kernel<<<BB, 256>>>(Wfc, bfc, out);
}

// round 9
// speedup vs baseline: 1.3848x; 1.0015x over previous
#include <cuda_runtime.h>
#include <math.h>

#define BB 64
#define TT 512
#define FF 64
#define EE 256
#define HH 512
#define GG 2048   // 4*H
#define OO 128
#define NBLK 128

// ---------------- device scratch (no allocations allowed) ----------------
__device__ float g_xg[(size_t)TT * NBLK * 16 * 64];  // [t][blk][c(16)][b(64)]  256 MB
__device__ float g_Wc[GG * FF];                      // fused W_ih @ W_emb
__device__ float g_biasc[GG];
__device__ float g_h[2][HH * BB];                    // [buf][k][b]  k-major
__device__ float g_hsum[BB * HH];                    // [b][k]
struct BarCnt { unsigned v; unsigned pad[63]; };     // 256B apart -> distinct L2 sets
__device__ BarCnt g_cnt[16];

// ---------------- f32x2 helpers ----------------
__device__ __forceinline__ void ffma2(unsigned long long& d, unsigned long long a,
                                      unsigned long long b) {
    asm("fma.rn.f32x2 %0, %1, %2, %3;" : "=l"(d) : "l"(a), "l"(b), "l"(d));
}
__device__ __forceinline__ unsigned long long dup2(float x) {
    unsigned long long r; unsigned u = __float_as_uint(x);
    asm("mov.b64 %0, {%1, %1};" : "=l"(r) : "r"(u));
    return r;
}
__device__ __forceinline__ float lo32(unsigned long long v) { return __uint_as_float((unsigned)v); }
__device__ __forceinline__ float hi32(unsigned long long v) { return __uint_as_float((unsigned)(v >> 32)); }

__device__ __forceinline__ void cpasync16(float* dst_smem, const float* src) {
    unsigned saddr = (unsigned)__cvta_generic_to_shared(dst_smem);
    asm volatile("cp.async.cg.shared.global [%0], [%1], 16;" :: "r"(saddr), "l"(src));
}
#define CP_COMMIT() asm volatile("cp.async.commit_group;")
#define CP_WAITN(n) asm volatile("cp.async.wait_group %0;" :: "n"(n))

__device__ __forceinline__ float ftanh(float x) {
    x = fminf(fmaxf(x, -15.f), 15.f);
    float e = __expf(2.f * x);
    return (e - 1.f) / (e + 1.f);
}
__device__ __forceinline__ float fsig(float x) { return 1.f / (1.f + __expf(-x)); }

// ---------------- 1. fuse weights: Wc = W_ih @ W_emb ----------------
__global__ void fuse_weights_kernel(const float* __restrict__ Wih,
                                    const float* __restrict__ Wemb,
                                    const float* __restrict__ bemb,
                                    const float* __restrict__ bih,
                                    const float* __restrict__ bhh) {
    int g = blockIdx.x;
    int f = threadIdx.x;
    __shared__ float s[EE];
    for (int e = f; e < EE; e += 64) s[e] = Wih[g * EE + e];
    __syncthreads();
    float acc = 0.f;
#pragma unroll 8
    for (int e = 0; e < EE; e++) acc += s[e] * Wemb[e * FF + f];
    g_Wc[g * FF + f] = acc;
    if (f == 0) {
        float bb = 0.f;
        for (int e = 0; e < EE; e++) bb += s[e] * bemb[e];
        g_biasc[g] = bb + bih[g] + bhh[g];
    }
}

// ---------------- 2. xg = x @ Wc^T + biasc, permuted out [t][blk][c][b] --------
__global__ __launch_bounds__(256) void xg_kernel(const float* __restrict__ x) {
    __shared__ __align__(16) float xs[FF][68];   // [k][b]
    __shared__ __align__(16) float ws[FF][68];   // [k][col]
    int tb = blockIdx.x;                  // token index t
    int cbase = blockIdx.y * 64;
    int tid = threadIdx.x;
#pragma unroll
    for (int i = 0; i < 16; i++) {
        int idx = i * 256 + tid;
        int r = idx >> 6, k = idx & 63;
        xs[k][r] = x[((size_t)r * TT + tb) * FF + k];           // b = r
        ws[k][r] = g_Wc[(size_t)(cbase + r) * FF + k];
    }
    __syncthreads();
    int rg = tid & 15, cg = tid >> 4;
    int r0 = rg * 4, c0 = cg * 4;
    unsigned long long acc[4][2] = {};
#pragma unroll 4
    for (int k = 0; k < FF; k++) {
        float4 hv = *(const float4*)&xs[k][r0];
        ulonglong2 wv = *(const ulonglong2*)&ws[k][c0];
        unsigned long long h0 = dup2(hv.x), h1 = dup2(hv.y), h2 = dup2(hv.z), h3 = dup2(hv.w);
        ffma2(acc[0][0], h0, wv.x); ffma2(acc[0][1], h0, wv.y);
        ffma2(acc[1][0], h1, wv.x); ffma2(acc[1][1], h1, wv.y);
        ffma2(acc[2][0], h2, wv.x); ffma2(acc[2][1], h2, wv.y);
        ffma2(acc[3][0], h3, wv.x); ffma2(acc[3][1], h3, wv.y);
    }
#pragma unroll
    for (int j = 0; j < 4; j++) {
        int g = cbase + c0 + j;
        float bias = g_biasc[g];
        int blk = (g & 511) >> 2;
        int cc = ((g >> 9) << 2) + (g & 3);
        float4 v;
        v.x = ((j & 1) ? hi32(acc[0][j >> 1]) : lo32(acc[0][j >> 1])) + bias;
        v.y = ((j & 1) ? hi32(acc[1][j >> 1]) : lo32(acc[1][j >> 1])) + bias;
        v.z = ((j & 1) ? hi32(acc[2][j >> 1]) : lo32(acc[2][j >> 1])) + bias;
        v.w = ((j & 1) ? hi32(acc[3][j >> 1]) : lo32(acc[3][j >> 1])) + bias;
        *(float4*)&g_xg[((((size_t)tb * NBLK + blk) * 16 + cc) << 6) + r0] = v;
    }
}

// ---------------- 3. init ----------------
__global__ void init_state_kernel() {
    int i = blockIdx.x * 256 + threadIdx.x;
    if (i < HH * BB) g_h[0][i] = 0.f;
    if (i < 16) g_cnt[i].v = 0u;
}

// ---------------- 4. persistent LSTM: all 512 steps in one kernel ------------
// 128 blocks x 256 threads. Block owns 4 hidden units (16 gate-cols).
// smem: W plain [512k][16c] 32KB | h [512k][64b] 128KB | red [8][64 str17][16] 34KB
// 8-way k-split; each warp pipelines its 64-k h slice in EIGHT 2KB cp.async
// groups, with an 8-way block-staggered chunk rotation so the 128-block h
// broadcast doesn't all hit the same L2 lines at once. Parallel-poll barrier.
__device__ __forceinline__ void gemm_chunk8(const float* __restrict__ wsl,
                                            const float* __restrict__ hsl,
                                            int G, unsigned long long acc[4][4],
                                            int b0, int c0) {
    __syncwarp();
#pragma unroll
    for (int u = 0; u < 8; u++) {
        int kk = G * 8 + u;
        float4 wv = *(const float4*)&wsl[kk * 16 + c0];
        unsigned long long w0 = dup2(wv.x), w1 = dup2(wv.y),
                           w2 = dup2(wv.z), w3 = dup2(wv.w);
        ulonglong2 hA = *(const ulonglong2*)&hsl[kk * 64 + b0];
        ulonglong2 hB = *(const ulonglong2*)&hsl[kk * 64 + b0 + 4];
        ffma2(acc[0][0], hA.x, w0); ffma2(acc[0][1], hA.x, w1);
        ffma2(acc[0][2], hA.x, w2); ffma2(acc[0][3], hA.x, w3);
        ffma2(acc[1][0], hA.y, w0); ffma2(acc[1][1], hA.y, w1);
        ffma2(acc[1][2], hA.y, w2); ffma2(acc[1][3], hA.y, w3);
        ffma2(acc[2][0], hB.x, w0); ffma2(acc[2][1], hB.x, w1);
        ffma2(acc[2][2], hB.x, w2); ffma2(acc[2][3], hB.x, w3);
        ffma2(acc[3][0], hB.y, w0); ffma2(acc[3][1], hB.y, w1);
        ffma2(acc[3][2], hB.y, w2); ffma2(acc[3][3], hB.y, w3);
    }
}

__global__ __launch_bounds__(256, 1) void lstm_persist(const float* __restrict__ Whh) {
    extern __shared__ __align__(16) float smem[];
    float* ws  = smem;                 // 8192 floats
    float* hs  = smem + 8192;          // 32768 floats
    float* red = smem + 40960;         // 8*64*17 = 8704 floats

    int tid = threadIdx.x;
    int blk = blockIdx.x;
    int j0 = blk * 4;

    // GEMM mapping: warp kg owns k in [kg*64, kg*64+64)
    int kg = tid >> 5;                 // warp id 0..7
    int lane = tid & 31;
    int b0 = (lane & 7) * 8;           // 8 batches
    int c0 = (lane >> 3) * 4;          // 4 gate-cols

    // epilogue mapping: one thread per (b, jj)
    int eb = tid & 63, ejj = tid >> 6;

    int start = blk & 7;               // per-block chunk rotation

    // load W_hh slice (16 cols x 512 k), plain floats [k][16]
    for (int idx = tid; idx < 16 * 512; idx += 256) {
        int k = idx >> 4, c = idx & 15;
        int g = ((c >> 2) << 9) + j0 + (c & 3);   // gate*512 + j
        ws[k * 16 + c] = Whh[(size_t)g * HH + k];
    }
    __syncthreads();

    float c_reg = 0.f, hsum_reg = 0.f;

    const float* hsl = hs + kg * 4096;
    const float* wsl = ws + kg * 64 * 16;

    for (int t = 0; t < TT; t++) {
        const float* hcur = g_h[t & 1];
        float* hnxt = g_h[(t + 1) & 1];

        // prefetch this step's xg gate values (consumed ~5k cyc later)
        const float* xp = g_xg + (size_t)t * (NBLK * 1024) + ((size_t)blk * 16 + ejj) * 64 + eb;
        float xv0 = __ldcg(xp), xv1 = __ldcg(xp + 256), xv2 = __ldcg(xp + 512), xv3 = __ldcg(xp + 768);

        // issue warp-private h slice load as 8 pipelined 2KB groups, rotated by blk
        {
            int base = kg * 4096;
#pragma unroll
            for (int i = 0; i < 8; i++) {
                int g = (start + i) & 7;
#pragma unroll
                for (int q = 0; q < 4; q++) {
                    int off = base + g * 512 + (q * 32 + lane) * 4;
                    cpasync16(hs + off, hcur + off);
                }
                CP_COMMIT();
            }
        }

        unsigned long long acc[4][4] = {};   // [batch-pair][col]

        CP_WAITN(7); gemm_chunk8(wsl, hsl, (start + 0) & 7, acc, b0, c0);
        CP_WAITN(6); gemm_chunk8(wsl, hsl, (start + 1) & 7, acc, b0, c0);
        CP_WAITN(5); gemm_chunk8(wsl, hsl, (start + 2) & 7, acc, b0, c0);
        CP_WAITN(4); gemm_chunk8(wsl, hsl, (start + 3) & 7, acc, b0, c0);
        CP_WAITN(3); gemm_chunk8(wsl, hsl, (start + 4) & 7, acc, b0, c0);
        CP_WAITN(2); gemm_chunk8(wsl, hsl, (start + 5) & 7, acc, b0, c0);
        CP_WAITN(1); gemm_chunk8(wsl, hsl, (start + 6) & 7, acc, b0, c0);
        CP_WAITN(0); gemm_chunk8(wsl, hsl, (start + 7) & 7, acc, b0, c0);

        // k-group partials -> red[kg][b][c] (stride 17 to avoid bank conflicts)
#pragma unroll
        for (int p = 0; p < 4; p++) {
            float* r0p = red + kg * 1088 + (b0 + 2 * p) * 17 + c0;
            float* r1p = r0p + 17;
#pragma unroll
            for (int j = 0; j < 4; j++) {
                r0p[j] = lo32(acc[p][j]);
                r1p[j] = hi32(acc[p][j]);
            }
        }
        __syncthreads();

        // epilogue: reduce 8 k-groups, activations, state update
        float gs0 = 0.f, gs1 = 0.f, gs2 = 0.f, gs3 = 0.f;
#pragma unroll
        for (int q = 0; q < 8; q++) {
            const float* rr = red + q * 1088 + eb * 17 + ejj;
            gs0 += rr[0]; gs1 += rr[4]; gs2 += rr[8]; gs3 += rr[12];
        }
        float iv = fsig(gs0 + xv0);
        float fv = fsig(gs1 + xv1);
        float gv = ftanh(gs2 + xv2);
        float ov = fsig(gs3 + xv3);
        c_reg = fv * c_reg + iv * gv;
        float hn = ov * ftanh(c_reg);
        hnxt[(j0 + ejj) * 64 + eb] = hn;   // [k][b] coalesced
        hsum_reg += hn;

        // grid barrier: arrive on 16 distributed counters, parallel-poll all 16
        if (t < TT - 1) {
            __threadfence();               // release h stores
            __syncthreads();               // all threads' stores fenced
            if (tid == 0) atomicAdd(&g_cnt[blk & 15].v, 1u);
            if (tid < 16) {
                unsigned want = 8u * (unsigned)(t + 1);
                while (*(volatile unsigned*)&g_cnt[tid].v < want) { }
            }
            __syncthreads();
            __threadfence();
        }
    }
    g_hsum[eb * HH + j0 + ejj] = hsum_reg;
}

// ---------------- 5. pooled = hsum/512 ; out = pooled @ W_fc^T + b_fc --------
__global__ void pool_fc_kernel(const float* __restrict__ Wfc,
                               const float* __restrict__ bfc,
                               float* __restrict__ out) {
    int b = blockIdx.x;
    __shared__ float sh[HH];
    int tid = threadIdx.x;
    for (int k = tid; k < HH; k += 256) sh[k] = g_hsum[b * HH + k];
    __syncthreads();
    int warp = tid >> 5, lane = tid & 31;
    for (int o = warp; o < OO; o += 8) {
        float a = 0.f;
        for (int k = lane; k < HH; k += 32) a += sh[k] * Wfc[o * HH + k];
#pragma unroll
        for (int s = 16; s; s >>= 1) a += __shfl_xor_sync(0xffffffffu, a, s);
        if (lane == 0) out[b * OO + o] = a * (1.f / 512.f) + bfc[o];
    }
}

extern "C" void kernel_launch(void* const* d_in, const int* in_sizes, int n_in,
                              void* d_out, int out_size) {
    const float* x    = (const float*)d_in[0];
    const float* Wemb = (const float*)d_in[1];
    const float* bemb = (const float*)d_in[2];
    const float* Wih  = (const float*)d_in[3];
    const float* Whh  = (const float*)d_in[4];
    const float* bih  = (const float*)d_in[5];
    const float* bhh  = (const float*)d_in[6];
    const float* Wfc  = (const float*)d_in[7];
    const float* bfc  = (const float*)d_in[8];
    float* out = (float*)d_out;

    static bool attr_set = false;
    if (!attr_set) {
        cudaFuncSetAttribute(lstm_persist, cudaFuncAttributeMaxDynamicSharedMemorySize, 198656);
        attr_set = true;
    }

    fuse_weights_kernel<<<GG, 64>>>(Wih, Wemb, bemb, bih, bhh);

    dim3 xgrid(TT, GG / 64);
    xg_kernel<<<xgrid, 256>>>(x);

    init_state_kernel<<<(HH * BB + 255) / 256, 256>>>();

    lstm_persist<<<NBLK, 256, 198656>>>(Whh);

    pool_fc_kernel<<<BB, 256>>>(Wfc, bfc, out);
}